// round 13
// baseline (speedup 1.0000x reference)
#include <cuda_runtime.h>
#include <math.h>

#define NPATCH 625
#define NA 60
#define NW 128
#define NHW 7680
#define NC1 32
#define NC2 64
#define NK 25

#define IN_STR 135
#define C1_STR 137
#define C2_STR 137
#define W2_STR 289

#define SM_W2 (NC2*W2_STR)
#define SM_IN (NA*IN_STR)
#define SM_C1 (4*NC1*C1_STR)
#define SM_C2 (NC2*C2_STR)
#define SM_P3 (4*NW)
#define SM_W1 (NC1*9)
#define SM_W3 (NC2*9)
#define SM_FLOATS (SM_W2+SM_IN+SM_C1+SM_C2+SM_P3+SM_W1+SM_W3+NC1+NC2+8*NK)
#define SMEM_BYTES (SM_FLOATS*4 + (10*NA+2)*4)

__device__ float g_patchvals[NPATCH*NK];
__device__ float g_linrowsum[NK];
__device__ float g_lwT[NHW*NK];
__device__ int   g_ctr;

__global__ void rowsum_kernel(const float* __restrict__ lw){
    if (blockIdx.x == 0 && threadIdx.x == 0) g_ctr = 0;
    int k = blockIdx.x;
    float s = 0.f;
    for (int j = threadIdx.x; j < NHW; j += 256) s += lw[k*NHW + j];
    __shared__ float red[8];
    #pragma unroll
    for (int o = 16; o; o >>= 1) s += __shfl_down_sync(0xffffffffu, s, o);
    if ((threadIdx.x & 31) == 0) red[threadIdx.x >> 5] = s;
    __syncthreads();
    if (threadIdx.x == 0){
        float t = 0.f;
        #pragma unroll
        for (int i = 0; i < 8; i++) t += red[i];
        g_linrowsum[k] = t;
    }
}

__global__ void transpose_lw_kernel(const float* __restrict__ lw){
    int idx = blockIdx.x*256 + threadIdx.x;
    if (idx < NHW*NK){
        int j = idx / NK, k = idx - j*NK;
        g_lwT[idx] = lw[k*NHW + j];
    }
}

__global__ void __launch_bounds__(256, 1) patch_kernel(
    const float* __restrict__ sino,
    const float* __restrict__ w1g, const float* __restrict__ b1g,
    const float* __restrict__ w2g, const float* __restrict__ b2g,
    const float* __restrict__ w3g, const float* __restrict__ b3g,
    const float* __restrict__ lwg, const float* __restrict__ lbg,
    const int*  __restrict__ masks)
{
    extern __shared__ float sm[];
    float* s_w2 = sm;
    float* s_in = s_w2 + SM_W2;
    float* s_c1 = s_in + SM_IN;
    float* s_c2 = s_c1 + SM_C1;
    float* s_p3 = s_c2 + SM_C2;
    float* s_w1 = s_p3 + SM_P3;
    float* s_w3 = s_w1 + SM_W1;
    float* s_b1 = s_w3 + SM_W3;
    float* s_b2 = s_b1 + NC1;
    float* s_red = s_b2 + NC2;
    int* s_rlo  = (int*)(s_red + 8*NK);
    int* s_rhi  = s_rlo + NA;
    int* s_b1lo = s_rhi + NA;  int* s_b1hi = s_b1lo + NA;
    int* s_b2lo = s_b1hi + NA; int* s_b2hi = s_b2lo + NA;
    int* s_b3lo = s_b2hi + NA; int* s_b3hi = s_b3lo + NA;
    int* s_z2lo = s_b3hi + NA; int* s_z2hi = s_z2lo + NA;
    int* s_ctl  = s_z2hi + NA;   // [0]=bias flag, [1]=patch id

    const int tid = threadIdx.x;

    // ---- weights once per CTA
    for (int i = tid; i < NC2*288; i += 256){
        int oc = i / 288;
        s_w2[oc*W2_STR + (i - oc*288)] = w2g[i];
    }
    for (int i = tid; i < SM_W1; i += 256) s_w1[i] = w1g[i];
    for (int i = tid; i < SM_W3; i += 256) s_w3[i] = w3g[i];
    if (tid < NC1) s_b1[tid] = b1g[tid];
    if (tid < NC2) s_b2[tid] = b2g[tid];
    if (tid == 0) s_ctl[0] = 0;
    for (int i = tid; i < SM_P3; i += 256) s_p3[i] = 0.f;
    // full zero once per CTA: padding entries (offset 0 and >=129 in each row)
    // are never stored again (stores predicated to col<NW), so they stay 0.
    for (int i = tid; i < SM_C1; i += 256) s_c1[i] = 0.f;
    for (int i = tid; i < SM_C2; i += 256) s_c2[i] = 0.f;
    __syncthreads();
    if (tid < NC1 && s_b1[tid] != 0.f) atomicOr(&s_ctl[0], 1);
    if (tid < NC2 && s_b2[tid] != 0.f) atomicOr(&s_ctl[0], 1);
    const float b3 = b3g[0];
    __syncthreads();
    const bool dense = (s_ctl[0] != 0);

    while (true){
        if (tid == 0) s_ctl[1] = atomicAdd(&g_ctr, 1);
        __syncthreads();
        const int p = s_ctl[1];
        if (p >= NPATCH) break;
        const int* mp = masks + p*NHW;

        if (tid < NA){ s_rlo[tid] = 1 << 29; s_rhi[tid] = -1; }
        for (int i = tid; i < SM_IN; i += 256){
            int r = i / IN_STR, cc = i - r*IN_STR;
            float v = 0.f;
            if (cc >= 1 && cc <= NW){
                int c = cc - 1;
                v = sino[r*NW + c] * (float)mp[r*NW + c];
            }
            s_in[i] = v;
        }
        __syncthreads();

        if (tid < 4*NA){
            int r = tid >> 2, q = tid & 3;
            int lo = 1 << 29, hi = -1;
            const int* row = mp + r*NW + q*32;
            for (int c = 0; c < 32; c++){
                if (row[c] != 0){ int cc = q*32 + c; if (cc < lo) lo = cc; hi = cc; }
            }
            if (hi >= 0){ atomicMin(&s_rlo[r], lo); atomicMax(&s_rhi[r], hi); }
        }
        __syncthreads();

        // per-row bands (e=1,2,3)
        if (tid < NA){
            #pragma unroll
            for (int e = 1; e <= 3; ++e){
                int lo, hi;
                if (dense){ lo = 0; hi = NW - 1; }
                else {
                    int l = 1 << 29, h = -1;
                    int a0 = tid - e; if (a0 < 0) a0 = 0;
                    int a1 = tid + e; if (a1 > NA - 1) a1 = NA - 1;
                    for (int r = a0; r <= a1; r++){
                        int rh = s_rhi[r];
                        if (rh >= 0){ int rl = s_rlo[r]; if (rl < l) l = rl; if (rh > h) h = rh; }
                    }
                    if (h < 0){ lo = 1; hi = 0; }
                    else {
                        lo = l - e; if (lo < 0) lo = 0;
                        hi = h + e; if (hi > NW - 1) hi = NW - 1;
                    }
                }
                if (e == 1){ s_b1lo[tid] = lo; s_b1hi[tid] = hi; }
                else if (e == 2){ s_b2lo[tid] = lo; s_b2hi[tid] = hi; }
                else { s_b3lo[tid] = lo; s_b3hi[tid] = hi; }
            }
        }
        __syncthreads();

        // conv2 compute band z2(r): union of conv3 read ranges of rows r-1..r+1
        if (tid < NA){
            int lo = 1 << 29, hi = -1;
            #pragma unroll
            for (int d = -1; d <= 1; ++d){
                int r = tid + d;
                if (r < 0 || r >= NA) continue;
                int l = s_b3lo[r], h = s_b3hi[r];
                if (l <= h){ if (l - 1 < lo) lo = l - 1; if (h + 1 > hi) hi = h + 1; }
            }
            if (hi < 0){ s_z2lo[tid] = 1; s_z2hi[tid] = 0; }
            else {
                if (lo < 0) lo = 0;
                if (hi > NW - 1) hi = NW - 1;
                s_z2lo[tid] = lo; s_z2hi[tid] = hi;
            }
        }
        __syncthreads();

        float pv[NK];
        #pragma unroll
        for (int k = 0; k < NK; k++) pv[k] = 0.f;

        int rmin = 0, rmax = NA - 1;
        bool any = true;
        if (!dense){
            int l = NA, h = -1;
            for (int r = 0; r < NA; r++)
                if (s_rhi[r] >= 0){ if (r < l) l = r; h = r; }
            if (h < 0) any = false;
            else { rmin = l - 3; if (rmin < 0) rmin = 0; rmax = h + 3; if (rmax > NA - 1) rmax = NA - 1; }
        }

        if (any){
            for (int y = rmin - 2; y <= rmax + 4; ++y){
                const int rp = y - 2;   // conv2/conv3 row (lags conv1 by 2)
                const bool doC1 = (y >= 0 && y < NA && y <= rmax + 2);
                const bool doC2 = (rp >= 0 && rp < NA && rp >= rmin - 1 && rp <= rmax + 1);
                int lo2 = 1, hi2 = 0;
                if (doC2){ lo2 = s_z2lo[rp]; hi2 = s_z2hi[rp]; }

                // ============ PHASE AB (one barrier): conv1(y) + conv2(y-2)
                // conv1 row y over [min_d z2lo(y+d)-1, max_d z2hi(y+d)+8]:
                // covers every c1 col conv2 (rows y-1..y+1) can read.
                if (doC1){
                    int zlo = 1 << 29, zhi = -1;
                    #pragma unroll
                    for (int d = -1; d <= 1; ++d){
                        int rr2 = y + d;
                        if (rr2 < 0 || rr2 >= NA) continue;
                        int l = s_z2lo[rr2], h = s_z2hi[rr2];
                        if (l <= h){ if (l - 1 < zlo) zlo = l - 1; if (h + 8 > zhi) zhi = h + 8; }
                    }
                    if (zlo < 0) zlo = 0; if (zhi > NW - 1) zhi = NW - 1;
                    if (zhi >= zlo){
                        const int oc = tid & 31, g = tid >> 5;
                        const float bb = s_b1[oc];
                        const float* wrow = s_w1 + oc*9;
                        float* dst = s_c1 + (y & 3)*(NC1*C1_STR) + oc*C1_STR + 1;
                        for (int cb = zlo + g*4; cb <= zhi; cb += 32){
                            float a0 = bb, a1 = bb, a2 = bb, a3 = bb;
                            #pragma unroll
                            for (int dy = 0; dy < 3; ++dy){
                                int yy = y + dy - 1;
                                if (yy < 0 || yy >= NA) continue;
                                const float* irow = s_in + yy*IN_STR + 1 + cb;
                                float w0 = wrow[dy*3+0], w1v = wrow[dy*3+1], w2v = wrow[dy*3+2];
                                float im1 = irow[-1], i0 = irow[0], i1 = irow[1],
                                      i2 = irow[2], i3 = irow[3], i4 = irow[4];
                                a0 += im1*w0 + i0*w1v + i1*w2v;
                                a1 += i0*w0 + i1*w1v + i2*w2v;
                                a2 += i1*w0 + i2*w1v + i3*w2v;
                                a3 += i2*w0 + i3*w1v + i4*w2v;
                            }
                            dst[cb+0] = fmaxf(a0, 0.f);
                            if (cb+1 < NW) dst[cb+1] = fmaxf(a1, 0.f);
                            if (cb+2 < NW) dst[cb+2] = fmaxf(a2, 0.f);
                            if (cb+3 < NW) dst[cb+3] = fmaxf(a3, 0.f);
                        }
                    }
                }
                // conv2 row rp over z2(rp): every col conv3 reads is freshly written
                if (doC2 && lo2 <= hi2){
                    const int oc = tid & 63, g = tid >> 6;
                    const float* wbase = s_w2 + oc*W2_STR;
                    const float bb = s_b2[oc];
                    float* dst = s_c2 + oc*C2_STR + 1;
                    for (int cb = lo2 + g*8; cb <= hi2; cb += 32){
                        float acc[8];
                        #pragma unroll
                        for (int j = 0; j < 8; j++) acc[j] = bb;
                        #pragma unroll
                        for (int dy = 0; dy < 3; ++dy){
                            int yy = rp + dy - 1;
                            if (yy < 0 || yy >= NA) continue;
                            const float* c1b = s_c1 + (yy & 3)*(NC1*C1_STR) + 1 + cb;
                            const float* wp = wbase + dy*3;
                            #pragma unroll 4
                            for (int ic = 0; ic < NC1; ++ic){
                                const float* rr = c1b + ic*C1_STR;
                                float w0 = wp[ic*9+0], w1v = wp[ic*9+1], w2v = wp[ic*9+2];
                                float prev = rr[-1], cur = rr[0];
                                #pragma unroll
                                for (int j = 0; j < 8; ++j){
                                    float nxt = rr[j+1];
                                    acc[j] += prev*w0 + cur*w1v + nxt*w2v;
                                    prev = cur; cur = nxt;
                                }
                            }
                        }
                        #pragma unroll
                        for (int j = 0; j < 8; ++j)
                            if (cb+j < NW) dst[cb+j] = fmaxf(acc[j], 0.f);
                    }
                }
                __syncthreads();

                // ============ PHASE C: conv3(rp) into p3 ring + finalize row y-4
                if (doC2 && lo2 <= hi2){
                    const int dd = tid >> 6;     // 0..3 (3 used)
                    const int cf = tid & 63;
                    if (dd < 3){
                        int tr = rp - 1 + dd;
                        if (tr >= rmin && tr <= rmax && tr >= 0 && tr < NA){
                            int lo3 = s_b3lo[tr], hi3 = s_b3hi[tr];
                            float* p3row = s_p3 + (tr & 3)*NW;
                            const int wsel = (2 - dd)*3;
                            for (int c = lo3 + cf; c <= hi3; c += 64){
                                float s = 0.f;
                                const float* c2p = s_c2 + 1 + c;
                                const float* w3p = s_w3 + wsel;
                                #pragma unroll 8
                                for (int oc = 0; oc < NC2; ++oc){
                                    s += c2p[oc*C2_STR - 1]*w3p[oc*9+0]
                                       + c2p[oc*C2_STR    ]*w3p[oc*9+1]
                                       + c2p[oc*C2_STR + 1]*w3p[oc*9+2];
                                }
                                p3row[c] += s;
                            }
                        }
                    }
                }
                {
                    int rfin = y - 4;
                    if (rfin >= rmin && rfin <= rmax && rfin >= 0 && rfin < NA){
                        int lo3 = s_b3lo[rfin], hi3 = s_b3hi[rfin];
                        if (lo3 <= hi3){
                            float* p3row = s_p3 + (rfin & 3)*NW;
                            for (int c = lo3 + tid; c <= hi3; c += 256){
                                float v = p3row[c];
                                p3row[c] = 0.f;
                                const float* lw = g_lwT + (rfin*NW + c)*NK;
                                #pragma unroll
                                for (int k = 0; k < NK; k++) pv[k] += v * lw[k];
                            }
                        }
                    }
                }
                __syncthreads();
            }
        }

        #pragma unroll
        for (int k = 0; k < NK; k++){
            float v = pv[k];
            #pragma unroll
            for (int o = 16; o; o >>= 1) v += __shfl_down_sync(0xffffffffu, v, o);
            if ((tid & 31) == 0) s_red[k*8 + (tid >> 5)] = v;
        }
        __syncthreads();
        if (tid < NK){
            float t = 0.f;
            #pragma unroll
            for (int i = 0; i < 8; i++) t += s_red[tid*8 + i];
            g_patchvals[p*NK + tid] = t + lbg[tid] + b3 * g_linrowsum[tid];
        }
        __syncthreads();
    }
}

__global__ void fill_kernel(float* __restrict__ out){
    int idx = blockIdx.x*256 + threadIdx.x;
    if (idx < NW*NW) out[idx] = 0.5f;
}

__global__ void scatter_kernel(const int* __restrict__ starts, float* __restrict__ out){
    int p = blockIdx.x, t = threadIdx.x;
    if (t < NK){
        int i = starts[p*2], j = starts[p*2+1];
        int a = t / 5, b = t - a*5;
        float v = g_patchvals[p*NK + t];
        out[(i + a)*NW + (j + b)] = 1.f / (1.f + expf(-v));
    }
}

__global__ void radon_kernel(const float* __restrict__ img, float* __restrict__ shat){
    extern __shared__ float simg[];
    int a = blockIdx.x, t = threadIdx.x;
    for (int i = t; i < NW*NW; i += 128) simg[i] = img[i];
    __syncthreads();
    float ct = (float)cos((double)a * 0.017453292519943295);
    float st = (float)sin((double)a * 0.017453292519943295);
    const float c = 63.5f;
    float tc = (float)t - c;
    float sum = 0.f;
    for (int s = 0; s < NW; ++s){
        float sc = (float)s - c;
        float x = c + tc*ct - sc*st;
        float y = c + tc*st + sc*ct;
        int x0 = (int)floorf(x), y0 = (int)floorf(y);
        float wx = x - (float)x0, wy = y - (float)y0;
        float v00 = 0.f, v10 = 0.f, v01 = 0.f, v11 = 0.f;
        if (x0 >= 0 && x0 < NW){
            if (y0 >= 0 && y0 < NW) v00 = simg[y0*NW + x0];
            if (y0+1 >= 0 && y0+1 < NW) v01 = simg[(y0+1)*NW + x0];
        }
        if (x0+1 >= 0 && x0+1 < NW){
            if (y0 >= 0 && y0 < NW) v10 = simg[y0*NW + x0 + 1];
            if (y0+1 >= 0 && y0+1 < NW) v11 = simg[(y0+1)*NW + x0 + 1];
        }
        sum += v00*(1.f-wx)*(1.f-wy) + v10*wx*(1.f-wy) + v01*(1.f-wx)*wy + v11*wx*wy;
    }
    shat[a*NW + t] = sum;
}

extern "C" void kernel_launch(void* const* d_in, const int* in_sizes, int n_in,
                              void* d_out, int out_size) {
    const float* sino = (const float*)d_in[0];
    const float* w1 = (const float*)d_in[1];
    const float* b1 = (const float*)d_in[2];
    const float* w2 = (const float*)d_in[3];
    const float* b2 = (const float*)d_in[4];
    const float* w3 = (const float*)d_in[5];
    const float* b3 = (const float*)d_in[6];
    const float* lw = (const float*)d_in[7];
    const float* lb = (const float*)d_in[8];
    const int* masks = (const int*)d_in[9];
    const int* starts = (const int*)d_in[10];
    float* out = (float*)d_out;

    cudaFuncSetAttribute(patch_kernel, cudaFuncAttributeMaxDynamicSharedMemorySize, SMEM_BYTES);
    cudaFuncSetAttribute(radon_kernel, cudaFuncAttributeMaxDynamicSharedMemorySize, NW*NW*4);

    rowsum_kernel<<<NK, 256>>>(lw);
    transpose_lw_kernel<<<(NHW*NK + 255)/256, 256>>>(lw);
    patch_kernel<<<152, 256, SMEM_BYTES>>>(sino, w1, b1, w2, b2, w3, b3, lw, lb, masks);
    fill_kernel<<<(NW*NW + 255)/256, 256>>>(out);
    scatter_kernel<<<NPATCH, 32>>>(starts, out);
    radon_kernel<<<NA, 128, NW*NW*4>>>(out, out + NW*NW);
}

// round 15
// speedup vs baseline: 1.1245x; 1.1245x over previous
#include <cuda_runtime.h>
#include <math.h>

#define NPATCH 625
#define NA 60
#define NW 128
#define NHW 7680
#define NC1 32
#define NC2 64
#define NK 25

#define IN_STR 135
#define C1_STR 137
#define C2_STR 137
#define W2_STR 289

#define SM_W2 (NC2*W2_STR)
#define SM_IN (NA*IN_STR)
#define SM_C1 (3*NC1*C1_STR)
#define SM_C2 (NC2*C2_STR)
#define SM_P3 (4*NW)
#define SM_W1 (NC1*9)
#define SM_W3 (NC2*9)
#define SM_FLOATS (SM_W2+SM_IN+SM_C1+SM_C2+SM_P3+SM_W1+SM_W3+NC1+NC2+8*NK)
#define SMEM_BYTES (SM_FLOATS*4 + (8*NA+2)*4)

__device__ float g_patchvals[NPATCH*NK];
__device__ float g_linrowsum[NK];
__device__ float g_lwT[NHW*NK];
__device__ int   g_ctr;

__global__ void rowsum_kernel(const float* __restrict__ lw){
    if (blockIdx.x == 0 && threadIdx.x == 0) g_ctr = 0;
    int k = blockIdx.x;
    float s = 0.f;
    for (int j = threadIdx.x; j < NHW; j += 256) s += lw[k*NHW + j];
    __shared__ float red[8];
    #pragma unroll
    for (int o = 16; o; o >>= 1) s += __shfl_down_sync(0xffffffffu, s, o);
    if ((threadIdx.x & 31) == 0) red[threadIdx.x >> 5] = s;
    __syncthreads();
    if (threadIdx.x == 0){
        float t = 0.f;
        #pragma unroll
        for (int i = 0; i < 8; i++) t += red[i];
        g_linrowsum[k] = t;
    }
}

__global__ void transpose_lw_kernel(const float* __restrict__ lw){
    int idx = blockIdx.x*256 + threadIdx.x;
    if (idx < NHW*NK){
        int j = idx / NK, k = idx - j*NK;
        g_lwT[idx] = lw[k*NHW + j];
    }
}

__global__ void __launch_bounds__(256, 1) patch_kernel(
    const float* __restrict__ sino,
    const float* __restrict__ w1g, const float* __restrict__ b1g,
    const float* __restrict__ w2g, const float* __restrict__ b2g,
    const float* __restrict__ w3g, const float* __restrict__ b3g,
    const float* __restrict__ lwg, const float* __restrict__ lbg,
    const int*  __restrict__ masks)
{
    extern __shared__ float sm[];
    float* s_w2 = sm;
    float* s_in = s_w2 + SM_W2;
    float* s_c1 = s_in + SM_IN;
    float* s_c2 = s_c1 + SM_C1;
    float* s_p3 = s_c2 + SM_C2;
    float* s_w1 = s_p3 + SM_P3;
    float* s_w3 = s_w1 + SM_W1;
    float* s_b1 = s_w3 + SM_W3;
    float* s_b2 = s_b1 + NC1;
    float* s_red = s_b2 + NC2;
    int* s_rlo  = (int*)(s_red + 8*NK);
    int* s_rhi  = s_rlo + NA;
    int* s_b1lo = s_rhi + NA;  int* s_b1hi = s_b1lo + NA;
    int* s_b2lo = s_b1hi + NA; int* s_b2hi = s_b2lo + NA;
    int* s_b3lo = s_b2hi + NA; int* s_b3hi = s_b3lo + NA;
    int* s_ctl  = s_b3hi + NA;   // [0]=bias flag, [1]=patch id

    const int tid = threadIdx.x;

    // ---- weights once per CTA
    for (int i = tid; i < NC2*288; i += 256){
        int oc = i / 288;
        s_w2[oc*W2_STR + (i - oc*288)] = w2g[i];
    }
    for (int i = tid; i < SM_W1; i += 256) s_w1[i] = w1g[i];
    for (int i = tid; i < SM_W3; i += 256) s_w3[i] = w3g[i];
    if (tid < NC1) s_b1[tid] = b1g[tid];
    if (tid < NC2) s_b2[tid] = b2g[tid];
    if (tid == 0) s_ctl[0] = 0;
    for (int i = tid; i < SM_P3; i += 256) s_p3[i] = 0.f;
    // full zero once per CTA: padding cols (offset 0 and >=129) are never
    // stored again (stores predicated to col<NW), so they stay 0 forever.
    for (int i = tid; i < SM_C1; i += 256) s_c1[i] = 0.f;
    for (int i = tid; i < SM_C2; i += 256) s_c2[i] = 0.f;
    __syncthreads();
    if (tid < NC1 && s_b1[tid] != 0.f) atomicOr(&s_ctl[0], 1);
    if (tid < NC2 && s_b2[tid] != 0.f) atomicOr(&s_ctl[0], 1);
    const float b3 = b3g[0];
    __syncthreads();
    const bool dense = (s_ctl[0] != 0);

    while (true){
        if (tid == 0) s_ctl[1] = atomicAdd(&g_ctr, 1);
        __syncthreads();
        const int p = s_ctl[1];
        if (p >= NPATCH) break;
        const int* mp = masks + p*NHW;

        if (tid < NA){ s_rlo[tid] = 1 << 29; s_rhi[tid] = -1; }
        for (int i = tid; i < SM_IN; i += 256){
            int r = i / IN_STR, cc = i - r*IN_STR;
            float v = 0.f;
            if (cc >= 1 && cc <= NW){
                int c = cc - 1;
                v = sino[r*NW + c] * (float)mp[r*NW + c];
            }
            s_in[i] = v;
        }
        __syncthreads();

        if (tid < 4*NA){
            int r = tid >> 2, q = tid & 3;
            int lo = 1 << 29, hi = -1;
            const int* row = mp + r*NW + q*32;
            for (int c = 0; c < 32; c++){
                if (row[c] != 0){ int cc = q*32 + c; if (cc < lo) lo = cc; hi = cc; }
            }
            if (hi >= 0){ atomicMin(&s_rlo[r], lo); atomicMax(&s_rhi[r], hi); }
        }
        __syncthreads();

        // precompute per-row bands (e=1,2,3)
        if (tid < NA){
            #pragma unroll
            for (int e = 1; e <= 3; ++e){
                int lo, hi;
                if (dense){ lo = 0; hi = NW - 1; }
                else {
                    int l = 1 << 29, h = -1;
                    int a0 = tid - e; if (a0 < 0) a0 = 0;
                    int a1 = tid + e; if (a1 > NA - 1) a1 = NA - 1;
                    for (int r = a0; r <= a1; r++){
                        int rh = s_rhi[r];
                        if (rh >= 0){ int rl = s_rlo[r]; if (rl < l) l = rl; if (rh > h) h = rh; }
                    }
                    if (h < 0){ lo = 1; hi = 0; }
                    else {
                        lo = l - e; if (lo < 0) lo = 0;
                        hi = h + e; if (hi > NW - 1) hi = NW - 1;
                    }
                }
                if (e == 1){ s_b1lo[tid] = lo; s_b1hi[tid] = hi; }
                else if (e == 2){ s_b2lo[tid] = lo; s_b2hi[tid] = hi; }
                else { s_b3lo[tid] = lo; s_b3hi[tid] = hi; }
            }
        }
        __syncthreads();

        float pv[NK];
        #pragma unroll
        for (int k = 0; k < NK; k++) pv[k] = 0.f;

        int rmin = 0, rmax = NA - 1;
        bool any = true;
        if (!dense){
            int l = NA, h = -1;
            for (int r = 0; r < NA; r++)
                if (s_rhi[r] >= 0){ if (r < l) l = r; h = r; }
            if (h < 0) any = false;
            else { rmin = l - 3; if (rmin < 0) rmin = 0; rmax = h + 3; if (rmax > NA - 1) rmax = NA - 1; }
        }

        if (any){
            for (int y = rmin - 2; y <= rmax + 3; ++y){
                const int rp = y - 1;
                const bool doC1 = (y >= 0 && y < NA);
                const bool doC2 = (rp >= 0 && rp < NA && rp >= rmin - 1 && rp <= rmax + 1);
                int lo2 = 1, hi2 = 0;
                if (doC2){ lo2 = s_b2lo[rp]; hi2 = s_b2hi[rp]; }

                // ============ PHASE A (one barrier):
                // (i) finalize p3 row y-3 -> pv, zero slot
                {
                    int rfin = y - 3;
                    if (rfin >= rmin && rfin <= rmax && rfin >= 0 && rfin < NA){
                        int lo3 = s_b3lo[rfin], hi3 = s_b3hi[rfin];
                        if (lo3 <= hi3){
                            float* p3row = s_p3 + (rfin & 3)*NW;
                            for (int c = lo3 + tid; c <= hi3; c += 256){
                                float v = p3row[c];
                                p3row[c] = 0.f;
                                const float* lw = g_lwT + (rfin*NW + c)*NK;
                                #pragma unroll
                                for (int k = 0; k < NK; k++) pv[k] += v * lw[k];
                            }
                        }
                    }
                }
                // (ii) zero c2 over conv3-read range [b3lo-1, b3hi+1] of rows rp-1..rp+1
                if (doC2){
                    int zlo = 1 << 29, zhi = -1;
                    #pragma unroll
                    for (int d = -1; d <= 1; ++d){
                        int rr2 = rp + d;
                        if (rr2 < 0 || rr2 >= NA) continue;
                        int l = s_b3lo[rr2], h = s_b3hi[rr2];
                        if (l <= h){ if (l - 1 < zlo) zlo = l - 1; if (h + 1 > zhi) zhi = h + 1; }
                    }
                    if (zlo < 0) zlo = 0; if (zhi > NW - 1) zhi = NW - 1;
                    if (zhi >= zlo){
                        int wz = zhi - zlo + 1;
                        float* dst0 = s_c2 + 1 + zlo;
                        for (int i = tid; i < NC2*wz; i += 256){
                            int oc2 = i / wz;
                            dst0[oc2*C2_STR + (i - oc2*wz)] = 0.f;
                        }
                    }
                }
                // (iii) conv1 over widened range covering all conv2 reads of row y:
                // conv2 (4-col blocks) reads c1 cols up to b2hi+4 =>
                // range [min_d b2lo(y+d) - 1, max_d b2hi(y+d) + 4]
                if (doC1){
                    int zlo = 1 << 29, zhi = -1;
                    #pragma unroll
                    for (int d = -1; d <= 1; ++d){
                        int rr2 = y + d;
                        if (rr2 < 0 || rr2 >= NA) continue;
                        int l = s_b2lo[rr2], h = s_b2hi[rr2];
                        if (l <= h){ if (l - 1 < zlo) zlo = l - 1; if (h + 4 > zhi) zhi = h + 4; }
                    }
                    if (zlo < 0) zlo = 0; if (zhi > NW - 1) zhi = NW - 1;
                    if (zhi >= zlo){
                        const int oc = tid & 31, g = tid >> 5;
                        const float bb = s_b1[oc];
                        const float* wrow = s_w1 + oc*9;
                        float* dst = s_c1 + (y % 3)*(NC1*C1_STR) + oc*C1_STR + 1;
                        for (int cb = zlo + g*4; cb <= zhi; cb += 32){
                            float a0 = bb, a1 = bb, a2 = bb, a3 = bb;
                            #pragma unroll
                            for (int dy = 0; dy < 3; ++dy){
                                int yy = y + dy - 1;
                                if (yy < 0 || yy >= NA) continue;
                                const float* irow = s_in + yy*IN_STR + 1 + cb;
                                float w0 = wrow[dy*3+0], w1v = wrow[dy*3+1], w2v = wrow[dy*3+2];
                                float im1 = irow[-1], i0 = irow[0], i1 = irow[1],
                                      i2 = irow[2], i3 = irow[3], i4 = irow[4];
                                a0 += im1*w0 + i0*w1v + i1*w2v;
                                a1 += i0*w0 + i1*w1v + i2*w2v;
                                a2 += i1*w0 + i2*w1v + i3*w2v;
                                a3 += i2*w0 + i3*w1v + i4*w2v;
                            }
                            // stores predicated to col < NW: keeps SAME-padding cols zero
                            dst[cb+0] = fmaxf(a0, 0.f);
                            if (cb+1 < NW) dst[cb+1] = fmaxf(a1, 0.f);
                            if (cb+2 < NW) dst[cb+2] = fmaxf(a2, 0.f);
                            if (cb+3 < NW) dst[cb+3] = fmaxf(a3, 0.f);
                        }
                    }
                }
                __syncthreads();

                // ============ PHASE B: conv2 over natural band, 4-col blocks (stride 16)
                if (doC2 && lo2 <= hi2){
                    const int oc = tid & 63, g = tid >> 6;
                    const float* wbase = s_w2 + oc*W2_STR;
                    const float bb = s_b2[oc];
                    float* dst = s_c2 + oc*C2_STR + 1;
                    for (int cb = lo2 + g*4; cb <= hi2; cb += 16){
                        float acc[4];
                        #pragma unroll
                        for (int j = 0; j < 4; j++) acc[j] = bb;
                        #pragma unroll
                        for (int dy = 0; dy < 3; ++dy){
                            int yy = rp + dy - 1;
                            if (yy < 0 || yy >= NA) continue;
                            const float* c1b = s_c1 + (yy % 3)*(NC1*C1_STR) + 1 + cb;
                            const float* wp = wbase + dy*3;
                            #pragma unroll 4
                            for (int ic = 0; ic < NC1; ++ic){
                                const float* rr = c1b + ic*C1_STR;
                                float w0 = wp[ic*9+0], w1v = wp[ic*9+1], w2v = wp[ic*9+2];
                                float prev = rr[-1], cur = rr[0];
                                #pragma unroll
                                for (int j = 0; j < 4; ++j){
                                    float nxt = rr[j+1];
                                    acc[j] += prev*w0 + cur*w1v + nxt*w2v;
                                    prev = cur; cur = nxt;
                                }
                            }
                        }
                        #pragma unroll
                        for (int j = 0; j < 4; ++j)
                            if (cb+j < NW) dst[cb+j] = fmaxf(acc[j], 0.f);
                    }
                }
                __syncthreads();

                // ============ PHASE C: conv3 into p3 ring (4 slots)
                if (doC2 && lo2 <= hi2){
                    const int dd = tid >> 6;     // 0..3 (3 used)
                    const int cf = tid & 63;
                    if (dd < 3){
                        int tr = rp - 1 + dd;
                        if (tr >= rmin && tr <= rmax && tr >= 0 && tr < NA){
                            int lo3 = s_b3lo[tr], hi3 = s_b3hi[tr];
                            float* p3row = s_p3 + (tr & 3)*NW;
                            const int wsel = (2 - dd)*3;
                            for (int c = lo3 + cf; c <= hi3; c += 64){
                                float s = 0.f;
                                const float* c2p = s_c2 + 1 + c;
                                const float* w3p = s_w3 + wsel;
                                #pragma unroll 8
                                for (int oc = 0; oc < NC2; ++oc){
                                    s += c2p[oc*C2_STR - 1]*w3p[oc*9+0]
                                       + c2p[oc*C2_STR    ]*w3p[oc*9+1]
                                       + c2p[oc*C2_STR + 1]*w3p[oc*9+2];
                                }
                                p3row[c] += s;
                            }
                        }
                    }
                }
                __syncthreads();
            }
        }

        #pragma unroll
        for (int k = 0; k < NK; k++){
            float v = pv[k];
            #pragma unroll
            for (int o = 16; o; o >>= 1) v += __shfl_down_sync(0xffffffffu, v, o);
            if ((tid & 31) == 0) s_red[k*8 + (tid >> 5)] = v;
        }
        __syncthreads();
        if (tid < NK){
            float t = 0.f;
            #pragma unroll
            for (int i = 0; i < 8; i++) t += s_red[tid*8 + i];
            g_patchvals[p*NK + tid] = t + lbg[tid] + b3 * g_linrowsum[tid];
        }
        __syncthreads();
    }
}

__global__ void fill_kernel(float* __restrict__ out){
    int idx = blockIdx.x*256 + threadIdx.x;
    if (idx < NW*NW) out[idx] = 0.5f;
}

__global__ void scatter_kernel(const int* __restrict__ starts, float* __restrict__ out){
    int p = blockIdx.x, t = threadIdx.x;
    if (t < NK){
        int i = starts[p*2], j = starts[p*2+1];
        int a = t / 5, b = t - a*5;
        float v = g_patchvals[p*NK + t];
        out[(i + a)*NW + (j + b)] = 1.f / (1.f + expf(-v));
    }
}

__global__ void radon_kernel(const float* __restrict__ img, float* __restrict__ shat){
    extern __shared__ float simg[];
    int a = blockIdx.x, t = threadIdx.x;
    for (int i = t; i < NW*NW; i += 128) simg[i] = img[i];
    __syncthreads();
    float ct = (float)cos((double)a * 0.017453292519943295);
    float st = (float)sin((double)a * 0.017453292519943295);
    const float c = 63.5f;
    float tc = (float)t - c;
    float sum = 0.f;
    for (int s = 0; s < NW; ++s){
        float sc = (float)s - c;
        float x = c + tc*ct - sc*st;
        float y = c + tc*st + sc*ct;
        int x0 = (int)floorf(x), y0 = (int)floorf(y);
        float wx = x - (float)x0, wy = y - (float)y0;
        float v00 = 0.f, v10 = 0.f, v01 = 0.f, v11 = 0.f;
        if (x0 >= 0 && x0 < NW){
            if (y0 >= 0 && y0 < NW) v00 = simg[y0*NW + x0];
            if (y0+1 >= 0 && y0+1 < NW) v01 = simg[(y0+1)*NW + x0];
        }
        if (x0+1 >= 0 && x0+1 < NW){
            if (y0 >= 0 && y0 < NW) v10 = simg[y0*NW + x0 + 1];
            if (y0+1 >= 0 && y0+1 < NW) v11 = simg[(y0+1)*NW + x0 + 1];
        }
        sum += v00*(1.f-wx)*(1.f-wy) + v10*wx*(1.f-wy) + v01*(1.f-wx)*wy + v11*wx*wy;
    }
    shat[a*NW + t] = sum;
}

extern "C" void kernel_launch(void* const* d_in, const int* in_sizes, int n_in,
                              void* d_out, int out_size) {
    const float* sino = (const float*)d_in[0];
    const float* w1 = (const float*)d_in[1];
    const float* b1 = (const float*)d_in[2];
    const float* w2 = (const float*)d_in[3];
    const float* b2 = (const float*)d_in[4];
    const float* w3 = (const float*)d_in[5];
    const float* b3 = (const float*)d_in[6];
    const float* lw = (const float*)d_in[7];
    const float* lb = (const float*)d_in[8];
    const int* masks = (const int*)d_in[9];
    const int* starts = (const int*)d_in[10];
    float* out = (float*)d_out;

    cudaFuncSetAttribute(patch_kernel, cudaFuncAttributeMaxDynamicSharedMemorySize, SMEM_BYTES);
    cudaFuncSetAttribute(radon_kernel, cudaFuncAttributeMaxDynamicSharedMemorySize, NW*NW*4);

    rowsum_kernel<<<NK, 256>>>(lw);
    transpose_lw_kernel<<<(NHW*NK + 255)/256, 256>>>(lw);
    patch_kernel<<<152, 256, SMEM_BYTES>>>(sino, w1, b1, w2, b2, w3, b3, lw, lb, masks);
    fill_kernel<<<(NW*NW + 255)/256, 256>>>(out);
    scatter_kernel<<<NPATCH, 32>>>(starts, out);
    radon_kernel<<<NA, 128, NW*NW*4>>>(out, out + NW*NW);
}

// round 16
// speedup vs baseline: 1.2137x; 1.0793x over previous
#include <cuda_runtime.h>
#include <math.h>

#define NPATCH 625
#define NA 60
#define NW 128
#define NHW 7680
#define NC1 32
#define NC2 64
#define NK 25

#define IN_STR 135
#define C1_STR 137
#define C2_STR 137
#define W2_STR 289

#define SM_W2 (NC2*W2_STR)
#define SM_IN (NA*IN_STR)
#define SM_C1 (3*NC1*C1_STR)
#define SM_C2 (NC2*C2_STR)
#define SM_P3 (4*NW)
#define SM_W1 (NC1*9)
#define SM_W3 (NC2*9)
#define SM_FLOATS (SM_W2+SM_IN+SM_C1+SM_C2+SM_P3+SM_W1+SM_W3+NC1+NC2+8*NK)
#define SMEM_BYTES (SM_FLOATS*4 + (8*NA+2)*4)

__device__ float g_patchvals[NPATCH*NK];
__device__ float g_linrowsum[NK];
__device__ float g_lwT[NHW*NK];
__device__ int   g_ctr;

__global__ void rowsum_kernel(const float* __restrict__ lw){
    if (blockIdx.x == 0 && threadIdx.x == 0) g_ctr = 0;
    int k = blockIdx.x;
    float s = 0.f;
    for (int j = threadIdx.x; j < NHW; j += 256) s += lw[k*NHW + j];
    __shared__ float red[8];
    #pragma unroll
    for (int o = 16; o; o >>= 1) s += __shfl_down_sync(0xffffffffu, s, o);
    if ((threadIdx.x & 31) == 0) red[threadIdx.x >> 5] = s;
    __syncthreads();
    if (threadIdx.x == 0){
        float t = 0.f;
        #pragma unroll
        for (int i = 0; i < 8; i++) t += red[i];
        g_linrowsum[k] = t;
    }
}

__global__ void transpose_lw_kernel(const float* __restrict__ lw){
    int idx = blockIdx.x*256 + threadIdx.x;
    if (idx < NHW*NK){
        int j = idx / NK, k = idx - j*NK;
        g_lwT[idx] = lw[k*NHW + j];
    }
}

// conv2 over one row with J-col register blocks; groups at stride 4*J.
template<int J>
__device__ __forceinline__ void conv2_row_t(
    const float* __restrict__ s_c1, const float* __restrict__ s_w2,
    float* __restrict__ s_c2, const float* __restrict__ s_b2,
    int rp, int lo2, int hi2, int tid)
{
    const int oc = tid & 63, g = tid >> 6;
    const float* wbase = s_w2 + oc*W2_STR;
    const float bb = s_b2[oc];
    float* dst = s_c2 + oc*C2_STR + 1;
    for (int cb = lo2 + g*J; cb <= hi2; cb += 4*J){
        float acc[J];
        #pragma unroll
        for (int j = 0; j < J; j++) acc[j] = bb;
        #pragma unroll
        for (int dy = 0; dy < 3; ++dy){
            int yy = rp + dy - 1;
            if (yy < 0 || yy >= NA) continue;
            const float* c1b = s_c1 + (yy % 3)*(NC1*C1_STR) + 1 + cb;
            const float* wp = wbase + dy*3;
            #pragma unroll 4
            for (int ic = 0; ic < NC1; ++ic){
                const float* rr = c1b + ic*C1_STR;
                float w0 = wp[ic*9+0], w1v = wp[ic*9+1], w2v = wp[ic*9+2];
                float prev = rr[-1], cur = rr[0];
                #pragma unroll
                for (int j = 0; j < J; ++j){
                    float nxt = rr[j+1];
                    acc[j] += prev*w0 + cur*w1v + nxt*w2v;
                    prev = cur; cur = nxt;
                }
            }
        }
        #pragma unroll
        for (int j = 0; j < J; ++j)
            if (cb+j < NW) dst[cb+j] = fmaxf(acc[j], 0.f);
    }
}

__global__ void __launch_bounds__(256, 1) patch_kernel(
    const float* __restrict__ sino,
    const float* __restrict__ w1g, const float* __restrict__ b1g,
    const float* __restrict__ w2g, const float* __restrict__ b2g,
    const float* __restrict__ w3g, const float* __restrict__ b3g,
    const float* __restrict__ lwg, const float* __restrict__ lbg,
    const int*  __restrict__ masks)
{
    extern __shared__ float sm[];
    float* s_w2 = sm;
    float* s_in = s_w2 + SM_W2;
    float* s_c1 = s_in + SM_IN;
    float* s_c2 = s_c1 + SM_C1;
    float* s_p3 = s_c2 + SM_C2;
    float* s_w1 = s_p3 + SM_P3;
    float* s_w3 = s_w1 + SM_W1;
    float* s_b1 = s_w3 + SM_W3;
    float* s_b2 = s_b1 + NC1;
    float* s_red = s_b2 + NC2;
    int* s_rlo  = (int*)(s_red + 8*NK);
    int* s_rhi  = s_rlo + NA;
    int* s_b1lo = s_rhi + NA;  int* s_b1hi = s_b1lo + NA;
    int* s_b2lo = s_b1hi + NA; int* s_b2hi = s_b2lo + NA;
    int* s_b3lo = s_b2hi + NA; int* s_b3hi = s_b3lo + NA;
    int* s_ctl  = s_b3hi + NA;   // [0]=bias flag, [1]=patch id

    const int tid = threadIdx.x;

    // ---- weights once per CTA
    for (int i = tid; i < NC2*288; i += 256){
        int oc = i / 288;
        s_w2[oc*W2_STR + (i - oc*288)] = w2g[i];
    }
    for (int i = tid; i < SM_W1; i += 256) s_w1[i] = w1g[i];
    for (int i = tid; i < SM_W3; i += 256) s_w3[i] = w3g[i];
    if (tid < NC1) s_b1[tid] = b1g[tid];
    if (tid < NC2) s_b2[tid] = b2g[tid];
    if (tid == 0) s_ctl[0] = 0;
    for (int i = tid; i < SM_P3; i += 256) s_p3[i] = 0.f;
    // full zero once per CTA: padding cols (offset 0 and >=129) are never
    // stored again (stores predicated to col<NW), so they stay 0 forever.
    for (int i = tid; i < SM_C1; i += 256) s_c1[i] = 0.f;
    for (int i = tid; i < SM_C2; i += 256) s_c2[i] = 0.f;
    __syncthreads();
    if (tid < NC1 && s_b1[tid] != 0.f) atomicOr(&s_ctl[0], 1);
    if (tid < NC2 && s_b2[tid] != 0.f) atomicOr(&s_ctl[0], 1);
    const float b3 = b3g[0];
    __syncthreads();
    const bool dense = (s_ctl[0] != 0);

    while (true){
        if (tid == 0) s_ctl[1] = atomicAdd(&g_ctr, 1);
        __syncthreads();
        const int p = s_ctl[1];
        if (p >= NPATCH) break;
        const int* mp = masks + p*NHW;

        if (tid < NA){ s_rlo[tid] = 1 << 29; s_rhi[tid] = -1; }
        for (int i = tid; i < SM_IN; i += 256){
            int r = i / IN_STR, cc = i - r*IN_STR;
            float v = 0.f;
            if (cc >= 1 && cc <= NW){
                int c = cc - 1;
                v = sino[r*NW + c] * (float)mp[r*NW + c];
            }
            s_in[i] = v;
        }
        __syncthreads();

        if (tid < 4*NA){
            int r = tid >> 2, q = tid & 3;
            int lo = 1 << 29, hi = -1;
            const int* row = mp + r*NW + q*32;
            for (int c = 0; c < 32; c++){
                if (row[c] != 0){ int cc = q*32 + c; if (cc < lo) lo = cc; hi = cc; }
            }
            if (hi >= 0){ atomicMin(&s_rlo[r], lo); atomicMax(&s_rhi[r], hi); }
        }
        __syncthreads();

        // precompute per-row bands (e=1,2,3)
        if (tid < NA){
            #pragma unroll
            for (int e = 1; e <= 3; ++e){
                int lo, hi;
                if (dense){ lo = 0; hi = NW - 1; }
                else {
                    int l = 1 << 29, h = -1;
                    int a0 = tid - e; if (a0 < 0) a0 = 0;
                    int a1 = tid + e; if (a1 > NA - 1) a1 = NA - 1;
                    for (int r = a0; r <= a1; r++){
                        int rh = s_rhi[r];
                        if (rh >= 0){ int rl = s_rlo[r]; if (rl < l) l = rl; if (rh > h) h = rh; }
                    }
                    if (h < 0){ lo = 1; hi = 0; }
                    else {
                        lo = l - e; if (lo < 0) lo = 0;
                        hi = h + e; if (hi > NW - 1) hi = NW - 1;
                    }
                }
                if (e == 1){ s_b1lo[tid] = lo; s_b1hi[tid] = hi; }
                else if (e == 2){ s_b2lo[tid] = lo; s_b2hi[tid] = hi; }
                else { s_b3lo[tid] = lo; s_b3hi[tid] = hi; }
            }
        }
        __syncthreads();

        float pv[NK];
        #pragma unroll
        for (int k = 0; k < NK; k++) pv[k] = 0.f;

        int rmin = 0, rmax = NA - 1;
        bool any = true;
        if (!dense){
            int l = NA, h = -1;
            for (int r = 0; r < NA; r++)
                if (s_rhi[r] >= 0){ if (r < l) l = r; h = r; }
            if (h < 0) any = false;
            else { rmin = l - 3; if (rmin < 0) rmin = 0; rmax = h + 3; if (rmax > NA - 1) rmax = NA - 1; }
        }

        if (any){
            for (int y = rmin - 2; y <= rmax + 3; ++y){
                const int rp = y - 1;
                const bool doC1 = (y >= 0 && y < NA);
                const bool doC2 = (rp >= 0 && rp < NA && rp >= rmin - 1 && rp <= rmax + 1);
                int lo2 = 1, hi2 = 0;
                if (doC2){ lo2 = s_b2lo[rp]; hi2 = s_b2hi[rp]; }

                // ============ PHASE A (one barrier):
                // (i) finalize p3 row y-3 -> pv, zero slot
                {
                    int rfin = y - 3;
                    if (rfin >= rmin && rfin <= rmax && rfin >= 0 && rfin < NA){
                        int lo3 = s_b3lo[rfin], hi3 = s_b3hi[rfin];
                        if (lo3 <= hi3){
                            float* p3row = s_p3 + (rfin & 3)*NW;
                            for (int c = lo3 + tid; c <= hi3; c += 256){
                                float v = p3row[c];
                                p3row[c] = 0.f;
                                const float* lw = g_lwT + (rfin*NW + c)*NK;
                                #pragma unroll
                                for (int k = 0; k < NK; k++) pv[k] += v * lw[k];
                            }
                        }
                    }
                }
                // (ii) zero c2 over conv3-read range [b3lo-1, b3hi+1] of rows rp-1..rp+1
                if (doC2){
                    int zlo = 1 << 29, zhi = -1;
                    #pragma unroll
                    for (int d = -1; d <= 1; ++d){
                        int rr2 = rp + d;
                        if (rr2 < 0 || rr2 >= NA) continue;
                        int l = s_b3lo[rr2], h = s_b3hi[rr2];
                        if (l <= h){ if (l - 1 < zlo) zlo = l - 1; if (h + 1 > zhi) zhi = h + 1; }
                    }
                    if (zlo < 0) zlo = 0; if (zhi > NW - 1) zhi = NW - 1;
                    if (zhi >= zlo){
                        int wz = zhi - zlo + 1;
                        float* dst0 = s_c2 + 1 + zlo;
                        for (int i = tid; i < NC2*wz; i += 256){
                            int oc2 = i / wz;
                            dst0[oc2*C2_STR + (i - oc2*wz)] = 0.f;
                        }
                    }
                }
                // (iii) conv1 over widened range covering all conv2 reads of row y:
                // [min_d b2lo(y+d) - 1, max_d b2hi(y+d) + 8]  (covers J<=8 reads)
                if (doC1){
                    int zlo = 1 << 29, zhi = -1;
                    #pragma unroll
                    for (int d = -1; d <= 1; ++d){
                        int rr2 = y + d;
                        if (rr2 < 0 || rr2 >= NA) continue;
                        int l = s_b2lo[rr2], h = s_b2hi[rr2];
                        if (l <= h){ if (l - 1 < zlo) zlo = l - 1; if (h + 8 > zhi) zhi = h + 8; }
                    }
                    if (zlo < 0) zlo = 0; if (zhi > NW - 1) zhi = NW - 1;
                    if (zhi >= zlo){
                        const int oc = tid & 31, g = tid >> 5;
                        const float bb = s_b1[oc];
                        const float* wrow = s_w1 + oc*9;
                        float* dst = s_c1 + (y % 3)*(NC1*C1_STR) + oc*C1_STR + 1;
                        for (int cb = zlo + g*4; cb <= zhi; cb += 32){
                            float a0 = bb, a1 = bb, a2 = bb, a3 = bb;
                            #pragma unroll
                            for (int dy = 0; dy < 3; ++dy){
                                int yy = y + dy - 1;
                                if (yy < 0 || yy >= NA) continue;
                                const float* irow = s_in + yy*IN_STR + 1 + cb;
                                float w0 = wrow[dy*3+0], w1v = wrow[dy*3+1], w2v = wrow[dy*3+2];
                                float im1 = irow[-1], i0 = irow[0], i1 = irow[1],
                                      i2 = irow[2], i3 = irow[3], i4 = irow[4];
                                a0 += im1*w0 + i0*w1v + i1*w2v;
                                a1 += i0*w0 + i1*w1v + i2*w2v;
                                a2 += i1*w0 + i2*w1v + i3*w2v;
                                a3 += i2*w0 + i3*w1v + i4*w2v;
                            }
                            // stores predicated to col < NW: keeps SAME-padding cols zero
                            dst[cb+0] = fmaxf(a0, 0.f);
                            if (cb+1 < NW) dst[cb+1] = fmaxf(a1, 0.f);
                            if (cb+2 < NW) dst[cb+2] = fmaxf(a2, 0.f);
                            if (cb+3 < NW) dst[cb+3] = fmaxf(a3, 0.f);
                        }
                    }
                }
                __syncthreads();

                // ============ PHASE B: conv2, per-row adaptive block size J
                // (per-SMSP makespan table; selection uniform across CTA)
                if (doC2 && lo2 <= hi2){
                    int B = hi2 - lo2 + 1;
                    if (B <= 8)       conv2_row_t<4>(s_c1, s_w2, s_c2, s_b2, rp, lo2, hi2, tid);
                    else if (B <= 12) conv2_row_t<6>(s_c1, s_w2, s_c2, s_b2, rp, lo2, hi2, tid);
                    else if (B <= 16) conv2_row_t<8>(s_c1, s_w2, s_c2, s_b2, rp, lo2, hi2, tid);
                    else if (B <= 24) conv2_row_t<6>(s_c1, s_w2, s_c2, s_b2, rp, lo2, hi2, tid);
                    else              conv2_row_t<8>(s_c1, s_w2, s_c2, s_b2, rp, lo2, hi2, tid);
                }
                __syncthreads();

                // ============ PHASE C: conv3 into p3 ring (4 slots)
                if (doC2 && lo2 <= hi2){
                    const int dd = tid >> 6;     // 0..3 (3 used)
                    const int cf = tid & 63;
                    if (dd < 3){
                        int tr = rp - 1 + dd;
                        if (tr >= rmin && tr <= rmax && tr >= 0 && tr < NA){
                            int lo3 = s_b3lo[tr], hi3 = s_b3hi[tr];
                            float* p3row = s_p3 + (tr & 3)*NW;
                            const int wsel = (2 - dd)*3;
                            for (int c = lo3 + cf; c <= hi3; c += 64){
                                float s = 0.f;
                                const float* c2p = s_c2 + 1 + c;
                                const float* w3p = s_w3 + wsel;
                                #pragma unroll 8
                                for (int oc = 0; oc < NC2; ++oc){
                                    s += c2p[oc*C2_STR - 1]*w3p[oc*9+0]
                                       + c2p[oc*C2_STR    ]*w3p[oc*9+1]
                                       + c2p[oc*C2_STR + 1]*w3p[oc*9+2];
                                }
                                p3row[c] += s;
                            }
                        }
                    }
                }
                __syncthreads();
            }
        }

        #pragma unroll
        for (int k = 0; k < NK; k++){
            float v = pv[k];
            #pragma unroll
            for (int o = 16; o; o >>= 1) v += __shfl_down_sync(0xffffffffu, v, o);
            if ((tid & 31) == 0) s_red[k*8 + (tid >> 5)] = v;
        }
        __syncthreads();
        if (tid < NK){
            float t = 0.f;
            #pragma unroll
            for (int i = 0; i < 8; i++) t += s_red[tid*8 + i];
            g_patchvals[p*NK + tid] = t + lbg[tid] + b3 * g_linrowsum[tid];
        }
        __syncthreads();
    }
}

__global__ void fill_kernel(float* __restrict__ out){
    int idx = blockIdx.x*256 + threadIdx.x;
    if (idx < NW*NW) out[idx] = 0.5f;
}

__global__ void scatter_kernel(const int* __restrict__ starts, float* __restrict__ out){
    int p = blockIdx.x, t = threadIdx.x;
    if (t < NK){
        int i = starts[p*2], j = starts[p*2+1];
        int a = t / 5, b = t - a*5;
        float v = g_patchvals[p*NK + t];
        out[(i + a)*NW + (j + b)] = 1.f / (1.f + expf(-v));
    }
}

__global__ void radon_kernel(const float* __restrict__ img, float* __restrict__ shat){
    extern __shared__ float simg[];
    int a = blockIdx.x, t = threadIdx.x;
    for (int i = t; i < NW*NW; i += 128) simg[i] = img[i];
    __syncthreads();
    float ct = (float)cos((double)a * 0.017453292519943295);
    float st = (float)sin((double)a * 0.017453292519943295);
    const float c = 63.5f;
    float tc = (float)t - c;
    float sum = 0.f;
    for (int s = 0; s < NW; ++s){
        float sc = (float)s - c;
        float x = c + tc*ct - sc*st;
        float y = c + tc*st + sc*ct;
        int x0 = (int)floorf(x), y0 = (int)floorf(y);
        float wx = x - (float)x0, wy = y - (float)y0;
        float v00 = 0.f, v10 = 0.f, v01 = 0.f, v11 = 0.f;
        if (x0 >= 0 && x0 < NW){
            if (y0 >= 0 && y0 < NW) v00 = simg[y0*NW + x0];
            if (y0+1 >= 0 && y0+1 < NW) v01 = simg[(y0+1)*NW + x0];
        }
        if (x0+1 >= 0 && x0+1 < NW){
            if (y0 >= 0 && y0 < NW) v10 = simg[y0*NW + x0 + 1];
            if (y0+1 >= 0 && y0+1 < NW) v11 = simg[(y0+1)*NW + x0 + 1];
        }
        sum += v00*(1.f-wx)*(1.f-wy) + v10*wx*(1.f-wy) + v01*(1.f-wx)*wy + v11*wx*wy;
    }
    shat[a*NW + t] = sum;
}

extern "C" void kernel_launch(void* const* d_in, const int* in_sizes, int n_in,
                              void* d_out, int out_size) {
    const float* sino = (const float*)d_in[0];
    const float* w1 = (const float*)d_in[1];
    const float* b1 = (const float*)d_in[2];
    const float* w2 = (const float*)d_in[3];
    const float* b2 = (const float*)d_in[4];
    const float* w3 = (const float*)d_in[5];
    const float* b3 = (const float*)d_in[6];
    const float* lw = (const float*)d_in[7];
    const float* lb = (const float*)d_in[8];
    const int* masks = (const int*)d_in[9];
    const int* starts = (const int*)d_in[10];
    float* out = (float*)d_out;

    cudaFuncSetAttribute(patch_kernel, cudaFuncAttributeMaxDynamicSharedMemorySize, SMEM_BYTES);
    cudaFuncSetAttribute(radon_kernel, cudaFuncAttributeMaxDynamicSharedMemorySize, NW*NW*4);

    rowsum_kernel<<<NK, 256>>>(lw);
    transpose_lw_kernel<<<(NHW*NK + 255)/256, 256>>>(lw);
    patch_kernel<<<152, 256, SMEM_BYTES>>>(sino, w1, b1, w2, b2, w3, b3, lw, lb, masks);
    fill_kernel<<<(NW*NW + 255)/256, 256>>>(out);
    scatter_kernel<<<NPATCH, 32>>>(starts, out);
    radon_kernel<<<NA, 128, NW*NW*4>>>(out, out + NW*NW);
}